// round 1
// baseline (speedup 1.0000x reference)
#include <cuda_runtime.h>
#include <math.h>

#define FIXED_FRAMES 30
#define N_SEL 107
#define N_LM 543

// Selected landmark indices: 40 lips, 21 left hand, 25 upper-body pose, 21 right hand
__constant__ int c_sel[N_SEL] = {
    61,185,40,39,37,0,267,269,270,409,291,
    146,91,181,84,17,314,405,321,375,
    78,191,80,81,82,13,312,311,310,415,
    95,88,178,87,14,317,402,318,324,308,
    // left hand 468..488
    468,469,470,471,472,473,474,475,476,477,478,479,480,481,482,483,484,485,486,487,488,
    // upper body pose 489..513
    489,490,491,492,493,494,495,496,497,498,499,500,501,502,503,504,505,506,507,508,509,510,511,512,513,
    // right hand 522..542
    522,523,524,525,526,527,528,529,530,531,532,533,534,535,536,537,538,539,540,541,542
};

__device__ double g_sum;
__device__ double g_sumsq;
__device__ unsigned long long g_cnt;

__global__ void init_kernel() {
    if (threadIdx.x == 0) {
        g_sum = 0.0;
        g_sumsq = 0.0;
        g_cnt = 0ull;
    }
}

// Single-pass nan-aware reduction: S = sum(x), Q = sum(x^2), cnt over non-NaN.
__global__ void reduce_kernel(const float4* __restrict__ xv, long long nvec,
                              const float* __restrict__ x, long long ntail) {
    float s = 0.0f, q = 0.0f;
    int cnt = 0;

    const long long stride = (long long)gridDim.x * blockDim.x;
    long long i = (long long)blockIdx.x * blockDim.x + threadIdx.x;

    // 4-deep manual unroll for MLP
    for (; i + 3 * stride < nvec; i += 4 * stride) {
        float4 a = xv[i];
        float4 b = xv[i + stride];
        float4 c = xv[i + 2 * stride];
        float4 d = xv[i + 3 * stride];
        #define ACC(v) { \
            float t0 = (v.x == v.x) ? v.x : 0.0f; cnt += (v.x == v.x); \
            float t1 = (v.y == v.y) ? v.y : 0.0f; cnt += (v.y == v.y); \
            float t2 = (v.z == v.z) ? v.z : 0.0f; cnt += (v.z == v.z); \
            float t3 = (v.w == v.w) ? v.w : 0.0f; cnt += (v.w == v.w); \
            s += t0 + t1 + t2 + t3; \
            q += t0*t0 + t1*t1 + t2*t2 + t3*t3; }
        ACC(a); ACC(b); ACC(c); ACC(d);
    }
    for (; i < nvec; i += stride) {
        float4 a = xv[i];
        ACC(a);
        #undef ACC
    }

    // scalar tail (total elements not divisible by 4) — thread 0 of block 0 only
    if (blockIdx.x == 0 && threadIdx.x == 0) {
        for (long long t = nvec * 4; t < nvec * 4 + ntail; t++) {
            float v = x[t];
            if (v == v) { s += v; q += v * v; cnt += 1; }
        }
    }

    // warp reduce
    for (int off = 16; off; off >>= 1) {
        s   += __shfl_down_sync(0xFFFFFFFFu, s, off);
        q   += __shfl_down_sync(0xFFFFFFFFu, q, off);
        cnt += __shfl_down_sync(0xFFFFFFFFu, cnt, off);
    }

    __shared__ float ss[8], sq[8];
    __shared__ int sc[8];
    int wid = threadIdx.x >> 5;
    int lid = threadIdx.x & 31;
    if (lid == 0) { ss[wid] = s; sq[wid] = q; sc[wid] = cnt; }
    __syncthreads();
    if (wid == 0) {
        int nw = blockDim.x >> 5;
        s   = (lid < nw) ? ss[lid] : 0.0f;
        q   = (lid < nw) ? sq[lid] : 0.0f;
        cnt = (lid < nw) ? sc[lid] : 0;
        for (int off = 4; off; off >>= 1) {
            s   += __shfl_down_sync(0xFFFFFFFFu, s, off);
            q   += __shfl_down_sync(0xFFFFFFFFu, q, off);
            cnt += __shfl_down_sync(0xFFFFFFFFu, cnt, off);
        }
        if (lid == 0) {
            atomicAdd(&g_sum, (double)s);
            atomicAdd(&g_sumsq, (double)q);
            atomicAdd(&g_cnt, (unsigned long long)cnt);
        }
    }
}

// Finalize stats + gather + resample. Output [30, 107, 3].
__global__ void gather_kernel(const float* __restrict__ x, float* __restrict__ out, int T) {
    int i = blockIdx.x * blockDim.x + threadIdx.x;
    const int OUT_N = FIXED_FRAMES * N_SEL * 3;
    if (i >= OUT_N) return;

    double S = g_sum;
    double Q = g_sumsq;
    double cnt = (double)g_cnt;
    double mean = S / cnt;
    double var = (Q - S * S / cnt) / (cnt - 1.0);
    float inv_std = (float)(1.0 / sqrt(var));
    float meanf = (float)mean;

    int f = i / (N_SEL * 3);
    int rem = i - f * (N_SEL * 3);
    int l = rem / 3;
    int c = rem - l * 3;
    int lm = c_sel[l];

    if (T >= FIXED_FRAMES) {
        // nearest-exact, matching f32 arithmetic of reference
        float scale = (float)((double)T / (double)FIXED_FRAMES);
        float pos = ((float)f + 0.5f) * scale;
        int idx = (int)floorf(pos);
        if (idx < 0) idx = 0;
        if (idx > T - 1) idx = T - 1;
        float v = x[(size_t)idx * (N_LM * 3) + lm * 3 + c];
        out[i] = (v == v) ? (v - meanf) * inv_std : 0.0f;
    } else {
        // linear, align_corners=False
        float scale = (float)((double)T / (double)FIXED_FRAMES);
        float pos = ((float)f + 0.5f) * scale - 0.5f;
        pos = fminf(fmaxf(pos, 0.0f), (float)(T - 1));
        int i0 = (int)floorf(pos);
        int i1 = min(i0 + 1, T - 1);
        float w = pos - (float)i0;
        float v0 = x[(size_t)i0 * (N_LM * 3) + lm * 3 + c];
        float v1 = x[(size_t)i1 * (N_LM * 3) + lm * 3 + c];
        float y0 = (v0 == v0) ? (v0 - meanf) * inv_std : 0.0f;
        float y1 = (v1 == v1) ? (v1 - meanf) * inv_std : 0.0f;
        out[i] = (1.0f - w) * y0 + w * y1;
    }
}

extern "C" void kernel_launch(void* const* d_in, const int* in_sizes, int n_in,
                              void* d_out, int out_size) {
    const float* x = (const float*)d_in[0];
    float* out = (float*)d_out;

    long long ntotal = (long long)in_sizes[0];
    int T = (int)(ntotal / (N_LM * 3));
    long long nvec = ntotal >> 2;          // float4 count
    long long ntail = ntotal & 3;

    init_kernel<<<1, 32>>>();

    int threads = 256;
    int blocks = 1184;  // 148 SMs * 8
    reduce_kernel<<<blocks, threads>>>((const float4*)x, nvec, x, ntail);

    const int OUT_N = FIXED_FRAMES * N_SEL * 3;  // 9630
    gather_kernel<<<(OUT_N + 255) / 256, 256>>>(x, out, T);
}